// round 2
// baseline (speedup 1.0000x reference)
#include <cuda_runtime.h>
#include <math.h>

#define BB 2
#define SS 2048
#define DD 1024
#define HH 16
#define HDD 64
#define MR (BB*SS)   // 4096 rows

// Scratch (allocation-free rule: __device__ globals)
__device__ __align__(16) float g_kv[MR * 2 * DD];  // 4096 x 2048
__device__ __align__(16) float g_q [MR * DD];      // 4096 x 1024
__device__ __align__(16) float g_av[MR * DD];      // 4096 x 1024 (B,H,S,HD layout!)

// ---------------------------------------------------------------------------
// Tiled fp32 GEMM: C[M,N] = A[M,K] @ B[K,N] + bias[N]
// BM=BN=128, BK=16, 256 threads, 8x8 per-thread micro-tile
// ---------------------------------------------------------------------------
#define GBM 128
#define GBN 128
#define GBK 16
#define GTM 8
#define GTN 8

__global__ __launch_bounds__(256) void gemm_bias_kernel(
    const float* __restrict__ A, const float* __restrict__ Bm,
    const float* __restrict__ bias, float* __restrict__ C,
    int M, int N, int K)
{
    __shared__ __align__(16) float As[GBK][GBM];
    __shared__ __align__(16) float Bs[GBK][GBN];

    const int tid  = threadIdx.x;
    const int brow = blockIdx.y * GBM;
    const int bcol = blockIdx.x * GBN;
    const int tr   = (tid / 16) * GTM;
    const int tc   = (tid % 16) * GTN;

    float acc[GTM][GTN];
    #pragma unroll
    for (int i = 0; i < GTM; i++)
        #pragma unroll
        for (int j = 0; j < GTN; j++) acc[i][j] = 0.f;

    for (int k0 = 0; k0 < K; k0 += GBK) {
        // Load A tile (128x16), store transposed into As[k][m]
        #pragma unroll
        for (int i = tid; i < GBM * GBK / 4; i += 256) {
            int r = i >> 2;            // / (GBK/4)
            int c = (i & 3) * 4;
            float4 a = *(const float4*)(A + (size_t)(brow + r) * K + k0 + c);
            As[c + 0][r] = a.x; As[c + 1][r] = a.y;
            As[c + 2][r] = a.z; As[c + 3][r] = a.w;
        }
        // Load B tile (16x128), coalesced float4
        #pragma unroll
        for (int i = tid; i < GBK * GBN / 4; i += 256) {
            int r = i >> 5;            // / (GBN/4)
            int c = (i & 31) * 4;
            *(float4*)(&Bs[r][c]) =
                *(const float4*)(Bm + (size_t)(k0 + r) * N + bcol + c);
        }
        __syncthreads();

        #pragma unroll
        for (int kk = 0; kk < GBK; kk++) {
            float4 a0 = *(const float4*)&As[kk][tr];
            float4 a1 = *(const float4*)&As[kk][tr + 4];
            float4 b0 = *(const float4*)&Bs[kk][tc];
            float4 b1 = *(const float4*)&Bs[kk][tc + 4];
            float af[GTM] = {a0.x, a0.y, a0.z, a0.w, a1.x, a1.y, a1.z, a1.w};
            float bf[GTN] = {b0.x, b0.y, b0.z, b0.w, b1.x, b1.y, b1.z, b1.w};
            #pragma unroll
            for (int i = 0; i < GTM; i++)
                #pragma unroll
                for (int j = 0; j < GTN; j++)
                    acc[i][j] += af[i] * bf[j];
        }
        __syncthreads();
    }

    // Epilogue: add bias, vectorized stores
    #pragma unroll
    for (int i = 0; i < GTM; i++) {
        float* crow = C + (size_t)(brow + tr + i) * N + bcol + tc;
        const float* brow_p = bias + bcol + tc;
        #pragma unroll
        for (int j4 = 0; j4 < GTN; j4 += 4) {
            float4 o;
            o.x = acc[i][j4 + 0] + brow_p[j4 + 0];
            o.y = acc[i][j4 + 1] + brow_p[j4 + 1];
            o.z = acc[i][j4 + 2] + brow_p[j4 + 2];
            o.w = acc[i][j4 + 3] + brow_p[j4 + 3];
            *(float4*)(crow + j4) = o;
        }
    }
}

// ---------------------------------------------------------------------------
// Fused flash attention (fp32, online softmax).
// Grid: (S/BQ, B*H). Block: 256 threads.
// Thread (r = tid/4, cg = tid%4): owns row r of the Q tile and a 16-wide
// column group of both the score tile and the output accumulator.
//
// NOTE: output is written in (B, H, S, HD) contiguous layout — the reference
// reshapes the (b,h,q,hd) einsum result straight to (b,s,d) WITHOUT
// transposing heads back, so the o-projection consumes head-major rows.
// ---------------------------------------------------------------------------
#define BQ 64
#define BKT 64
#define PSTRIDE 65   // padded row stride for p_s: kills 8-way bank conflict

__global__ __launch_bounds__(256) void attn_kernel(
    const float* __restrict__ q, const float* __restrict__ kv,
    float* __restrict__ out)
{
    extern __shared__ __align__(16) float sm[];
    float* k_s = sm;                       // [64][64]
    float* v_s = sm + BKT * HDD;           // [64][64]
    float* p_s = sm + 2 * BKT * HDD;       // [64][65]

    const int tid = threadIdx.x;
    const int r   = tid >> 2;
    const int cg  = tid & 3;
    const int bh  = blockIdx.y;
    const int b   = bh / HH;
    const int h   = bh % HH;
    const int q0  = blockIdx.x * BQ;

    // Load this thread's Q row into registers, pre-scaled by 1/sqrt(HD),
    // rotated by cg (matches the rotated k_s access below).
    const float scale = 0.125f;
    const float* qrow = q + ((size_t)(b * SS + q0 + r)) * DD + h * HDD;
    float4 qreg[16];
    #pragma unroll
    for (int d4 = 0; d4 < 16; d4++) {
        int ds = ((d4 + cg) & 15) * 4;
        float4 t = *(const float4*)(qrow + ds);
        qreg[d4] = make_float4(t.x * scale, t.y * scale, t.z * scale, t.w * scale);
    }

    float m = -INFINITY, l = 0.f;
    float oacc[16];
    #pragma unroll
    for (int o = 0; o < 16; o++) oacc[o] = 0.f;

    const size_t kvstride = (size_t)(2 * DD);
    const float* kvbase = kv + ((size_t)b * SS) * kvstride + h * 2 * HDD;

    for (int kt = 0; kt < SS; kt += BKT) {
        // Cooperative load of K and V tiles (64x64 each), coalesced float4
        #pragma unroll
        for (int i = tid; i < BKT * HDD / 4; i += 256) {
            int rr = i >> 4;            // / (HDD/4)
            int cc = (i & 15) * 4;
            const float* src = kvbase + (size_t)(kt + rr) * kvstride;
            *(float4*)(k_s + rr * HDD + cc) = *(const float4*)(src + cc);
            *(float4*)(v_s + rr * HDD + cc) = *(const float4*)(src + HDD + cc);
        }
        __syncthreads();

        // S = (Q/sqrt(d)) @ K^T : 16 scores per thread
        float sv[16];
        #pragma unroll
        for (int jj = 0; jj < 16; jj++) {
            const int j = cg * 16 + jj;
            const float4* krow = (const float4*)(k_s + j * HDD);
            float a0 = 0.f, a1 = 0.f, a2 = 0.f, a3 = 0.f;
            #pragma unroll
            for (int d4 = 0; d4 < 16; d4++) {
                float4 kk = krow[(d4 + cg) & 15];
                float4 qq = qreg[d4];
                a0 += qq.x * kk.x; a1 += qq.y * kk.y;
                a2 += qq.z * kk.z; a3 += qq.w * kk.w;
            }
            sv[jj] = (a0 + a1) + (a2 + a3);
        }

        // Online softmax: row max/sum across the 4 lanes sharing a row
        float mloc = sv[0];
        #pragma unroll
        for (int jj = 1; jj < 16; jj++) mloc = fmaxf(mloc, sv[jj]);
        mloc = fmaxf(mloc, __shfl_xor_sync(0xffffffffu, mloc, 1));
        mloc = fmaxf(mloc, __shfl_xor_sync(0xffffffffu, mloc, 2));
        const float mnew = fmaxf(m, mloc);
        const float corr = __expf(m - mnew);

        float lloc = 0.f;
        #pragma unroll
        for (int jj = 0; jj < 16; jj++) {
            sv[jj] = __expf(sv[jj] - mnew);
            lloc += sv[jj];
        }
        lloc += __shfl_xor_sync(0xffffffffu, lloc, 1);
        lloc += __shfl_xor_sync(0xffffffffu, lloc, 2);
        l = l * corr + lloc;
        m = mnew;
        #pragma unroll
        for (int o = 0; o < 16; o++) oacc[o] *= corr;

        // Publish p for this row (only the 4 lanes of this row consume it)
        #pragma unroll
        for (int jj = 0; jj < 16; jj++)
            p_s[r * PSTRIDE + cg * 16 + jj] = sv[jj];
        __syncwarp();

        // O += P @ V (thread owns 16 output dims, loops all 64 k-rows)
        #pragma unroll 4
        for (int j = 0; j < BKT; j++) {
            const float p = p_s[r * PSTRIDE + j];
            const float4* vrow = (const float4*)(v_s + j * HDD + cg * 16);
            float4 v0 = vrow[0], v1 = vrow[1], v2 = vrow[2], v3 = vrow[3];
            oacc[0]  += p * v0.x; oacc[1]  += p * v0.y;
            oacc[2]  += p * v0.z; oacc[3]  += p * v0.w;
            oacc[4]  += p * v1.x; oacc[5]  += p * v1.y;
            oacc[6]  += p * v1.z; oacc[7]  += p * v1.w;
            oacc[8]  += p * v2.x; oacc[9]  += p * v2.y;
            oacc[10] += p * v2.z; oacc[11] += p * v2.w;
            oacc[12] += p * v3.x; oacc[13] += p * v3.y;
            oacc[14] += p * v3.z; oacc[15] += p * v3.w;
        }
        __syncthreads();
    }

    // Normalize and store in (B, H, S, HD) contiguous layout (head-major),
    // matching the reference's direct reshape of (b,h,q,hd) -> (b,s,d).
    const float inv_l = 1.f / l;
    float* orow = out + ((size_t)((b * HH + h) * SS + q0 + r)) * HDD + cg * 16;
    #pragma unroll
    for (int o4 = 0; o4 < 4; o4++) {
        float4 t;
        t.x = oacc[4 * o4 + 0] * inv_l;
        t.y = oacc[4 * o4 + 1] * inv_l;
        t.z = oacc[4 * o4 + 2] * inv_l;
        t.w = oacc[4 * o4 + 3] * inv_l;
        *(float4*)(orow + o4 * 4) = t;
    }
}

// ---------------------------------------------------------------------------
extern "C" void kernel_launch(void* const* d_in, const int* in_sizes, int n_in,
                              void* d_out, int out_size)
{
    const float* x    = (const float*)d_in[0];
    const float* y    = (const float*)d_in[1];
    const float* W_kv = (const float*)d_in[2];
    const float* b_kv = (const float*)d_in[3];
    const float* W_q  = (const float*)d_in[4];
    const float* b_q  = (const float*)d_in[5];
    const float* W_o  = (const float*)d_in[6];
    const float* b_o  = (const float*)d_in[7];
    float* out = (float*)d_out;

    float *kvp, *qp, *avp;
    cudaGetSymbolAddress((void**)&kvp, g_kv);
    cudaGetSymbolAddress((void**)&qp,  g_q);
    cudaGetSymbolAddress((void**)&avp, g_av);

    dim3 blk(256);

    // kv = x @ W_kv + b_kv   [4096 x 2048]
    gemm_bias_kernel<<<dim3((2 * DD) / GBN, MR / GBM), blk>>>(
        x, W_kv, b_kv, kvp, MR, 2 * DD, DD);
    // q = y @ W_q + b_q      [4096 x 1024]
    gemm_bias_kernel<<<dim3(DD / GBN, MR / GBM), blk>>>(
        y, W_q, b_q, qp, MR, DD, DD);

    // fused attention -> values in (B,H,S,HD) layout [4096 x 1024]
    size_t shbytes = (size_t)(2 * BKT * HDD + BQ * PSTRIDE) * sizeof(float);
    cudaFuncSetAttribute(attn_kernel,
                         cudaFuncAttributeMaxDynamicSharedMemorySize,
                         (int)shbytes);
    attn_kernel<<<dim3(SS / BQ, BB * HH), blk, shbytes>>>(qp, kvp, avp);

    // out = values @ W_o + b_o [4096 x 1024]
    gemm_bias_kernel<<<dim3(DD / GBN, MR / GBM), blk>>>(
        avp, W_o, b_o, out, MR, DD, DD);
}

// round 3
// speedup vs baseline: 5.5728x; 5.5728x over previous
#include <cuda_runtime.h>
#include <math.h>

#define BB 2
#define SS 2048
#define DD 1024
#define HH 16
#define HDD 64
#define MR (BB*SS)   // 4096 rows

// Scratch (allocation-free rule: __device__ globals)
__device__ __align__(16) float g_kv[MR * 2 * DD];  // 4096 x 2048
__device__ __align__(16) float g_q [MR * DD];      // 4096 x 1024
__device__ __align__(16) float g_av[MR * DD];      // 4096 x 1024 (B,H,S,HD layout!)

// ---------------------------------------------------------------------------
// Tiled fp32 GEMM: C[M,N] = A[M,K] @ B[K,N] + bias[N]
// ---------------------------------------------------------------------------
#define GBM 128
#define GBN 128
#define GBK 16
#define GTM 8
#define GTN 8

__global__ __launch_bounds__(256) void gemm_bias_kernel(
    const float* __restrict__ A, const float* __restrict__ Bm,
    const float* __restrict__ bias, float* __restrict__ C,
    int M, int N, int K)
{
    __shared__ __align__(16) float As[GBK][GBM];
    __shared__ __align__(16) float Bs[GBK][GBN];

    const int tid  = threadIdx.x;
    const int brow = blockIdx.y * GBM;
    const int bcol = blockIdx.x * GBN;
    const int tr   = (tid / 16) * GTM;
    const int tc   = (tid % 16) * GTN;

    float acc[GTM][GTN];
    #pragma unroll
    for (int i = 0; i < GTM; i++)
        #pragma unroll
        for (int j = 0; j < GTN; j++) acc[i][j] = 0.f;

    for (int k0 = 0; k0 < K; k0 += GBK) {
        #pragma unroll
        for (int i = tid; i < GBM * GBK / 4; i += 256) {
            int r = i >> 2;
            int c = (i & 3) * 4;
            float4 a = *(const float4*)(A + (size_t)(brow + r) * K + k0 + c);
            As[c + 0][r] = a.x; As[c + 1][r] = a.y;
            As[c + 2][r] = a.z; As[c + 3][r] = a.w;
        }
        #pragma unroll
        for (int i = tid; i < GBK * GBN / 4; i += 256) {
            int r = i >> 5;
            int c = (i & 31) * 4;
            *(float4*)(&Bs[r][c]) =
                *(const float4*)(Bm + (size_t)(k0 + r) * N + bcol + c);
        }
        __syncthreads();

        #pragma unroll
        for (int kk = 0; kk < GBK; kk++) {
            float4 a0 = *(const float4*)&As[kk][tr];
            float4 a1 = *(const float4*)&As[kk][tr + 4];
            float4 b0 = *(const float4*)&Bs[kk][tc];
            float4 b1 = *(const float4*)&Bs[kk][tc + 4];
            float af[GTM] = {a0.x, a0.y, a0.z, a0.w, a1.x, a1.y, a1.z, a1.w};
            float bf[GTN] = {b0.x, b0.y, b0.z, b0.w, b1.x, b1.y, b1.z, b1.w};
            #pragma unroll
            for (int i = 0; i < GTM; i++)
                #pragma unroll
                for (int j = 0; j < GTN; j++)
                    acc[i][j] += af[i] * bf[j];
        }
        __syncthreads();
    }

    #pragma unroll
    for (int i = 0; i < GTM; i++) {
        float* crow = C + (size_t)(brow + tr + i) * N + bcol + tc;
        const float* brow_p = bias + bcol + tc;
        #pragma unroll
        for (int j4 = 0; j4 < GTN; j4 += 4) {
            float4 o;
            o.x = acc[i][j4 + 0] + brow_p[j4 + 0];
            o.y = acc[i][j4 + 1] + brow_p[j4 + 1];
            o.z = acc[i][j4 + 2] + brow_p[j4 + 2];
            o.w = acc[i][j4 + 3] + brow_p[j4 + 3];
            *(float4*)(crow + j4) = o;
        }
    }
}

// ---------------------------------------------------------------------------
// Tensor-core flash attention (tf32 mma.sync m16n8k8, fp32 accum).
// BQ=128 (8 warps x 16 rows), BK=64, HD=64.
// K tile in smem stride 68 (bank = 4g+8j+t : conflict-free B-frag reads)
// V tile in smem stride 72 (bank = 8t+g   : conflict-free B-frag reads)
// Both tiles stored pre-converted to tf32 bit patterns.
// Output written in (B, H, S, HD) contiguous layout (reference reshapes
// the (b,h,q,hd) einsum result directly without re-transposing heads).
// ---------------------------------------------------------------------------
#define KSTRIDE 68
#define VSTRIDE 72
#define FULLMASK 0xffffffffu

__device__ __forceinline__ unsigned f2tf32(float f) {
    unsigned u;
    asm("cvt.rna.tf32.f32 %0, %1;" : "=r"(u) : "f"(f));
    return u;
}

__device__ __forceinline__ void mma_tf32(float* d, const unsigned* a,
                                         unsigned b0, unsigned b1) {
    asm volatile(
        "mma.sync.aligned.m16n8k8.row.col.f32.tf32.tf32.f32 "
        "{%0,%1,%2,%3}, {%4,%5,%6,%7}, {%8,%9}, {%0,%1,%2,%3};\n"
        : "+f"(d[0]), "+f"(d[1]), "+f"(d[2]), "+f"(d[3])
        : "r"(a[0]), "r"(a[1]), "r"(a[2]), "r"(a[3]), "r"(b0), "r"(b1));
}

__global__ __launch_bounds__(256, 1) void attn_tc_kernel(
    const float* __restrict__ q, const float* __restrict__ kv,
    float* __restrict__ out)
{
    __shared__ unsigned k_u[64 * KSTRIDE];
    __shared__ unsigned v_u[64 * VSTRIDE];

    const int tid  = threadIdx.x;
    const int w    = tid >> 5;
    const int lane = tid & 31;
    const int g    = lane >> 2;   // group id (row within fragment)
    const int t    = lane & 3;    // thread-in-group
    const int bh   = blockIdx.y;
    const int b    = bh / HH;
    const int h    = bh % HH;
    const int q0   = blockIdx.x * 128;

    // ---- Q fragments (held in registers for the whole KV loop) ----
    unsigned qa[8][4];
    {
        const float* q0p = q + (size_t)(b * SS + q0 + w * 16 + g) * DD + h * HDD;
        const float* q1p = q0p + (size_t)8 * DD;
        #pragma unroll
        for (int kj = 0; kj < 8; kj++) {
            qa[kj][0] = f2tf32(q0p[8 * kj + t]     * 0.125f);
            qa[kj][1] = f2tf32(q1p[8 * kj + t]     * 0.125f);
            qa[kj][2] = f2tf32(q0p[8 * kj + t + 4] * 0.125f);
            qa[kj][3] = f2tf32(q1p[8 * kj + t + 4] * 0.125f);
        }
    }

    float o[8][4];
    #pragma unroll
    for (int i = 0; i < 8; i++)
        #pragma unroll
        for (int j = 0; j < 4; j++) o[i][j] = 0.f;
    float m0 = -INFINITY, m1 = -INFINITY, l0 = 0.f, l1 = 0.f;

    const float* kvbase = kv + (size_t)b * SS * (2 * DD) + h * (2 * HDD);

    for (int kt = 0; kt < SS; kt += 64) {
        // ---- cooperative K/V tile load, cvt to tf32 at store ----
        #pragma unroll
        for (int it = 0; it < 4; it++) {
            int idx = it * 256 + tid;
            int row = idx >> 4;
            int c4  = (idx & 15) * 4;
            const float* src = kvbase + (size_t)(kt + row) * (2 * DD) + c4;
            float4 kf = *(const float4*)src;
            float4 vf = *(const float4*)(src + HDD);
            uint4 ku = make_uint4(f2tf32(kf.x), f2tf32(kf.y),
                                  f2tf32(kf.z), f2tf32(kf.w));
            uint4 vu = make_uint4(f2tf32(vf.x), f2tf32(vf.y),
                                  f2tf32(vf.z), f2tf32(vf.w));
            *(uint4*)&k_u[row * KSTRIDE + c4] = ku;
            *(uint4*)&v_u[row * VSTRIDE + c4] = vu;
        }
        __syncthreads();

        // ---- S = (Q * scale) @ K^T : 8 n-tiles of 16x8 per warp ----
        float s[8][4];
        #pragma unroll
        for (int nt = 0; nt < 8; nt++) {
            s[nt][0] = s[nt][1] = s[nt][2] = s[nt][3] = 0.f;
            const unsigned* krow = &k_u[(8 * nt + g) * KSTRIDE];
            #pragma unroll
            for (int kj = 0; kj < 8; kj++) {
                unsigned b0 = krow[8 * kj + t];
                unsigned b1 = krow[8 * kj + t + 4];
                mma_tf32(s[nt], qa[kj], b0, b1);
            }
        }

        // ---- online softmax (rows r0 = 16w+g, r1 = r0+8) ----
        float rmax0 = -INFINITY, rmax1 = -INFINITY;
        #pragma unroll
        for (int nt = 0; nt < 8; nt++) {
            rmax0 = fmaxf(rmax0, fmaxf(s[nt][0], s[nt][1]));
            rmax1 = fmaxf(rmax1, fmaxf(s[nt][2], s[nt][3]));
        }
        rmax0 = fmaxf(rmax0, __shfl_xor_sync(FULLMASK, rmax0, 1));
        rmax0 = fmaxf(rmax0, __shfl_xor_sync(FULLMASK, rmax0, 2));
        rmax1 = fmaxf(rmax1, __shfl_xor_sync(FULLMASK, rmax1, 1));
        rmax1 = fmaxf(rmax1, __shfl_xor_sync(FULLMASK, rmax1, 2));

        const float mn0 = fmaxf(m0, rmax0);
        const float mn1 = fmaxf(m1, rmax1);
        const float cr0 = __expf(m0 - mn0);
        const float cr1 = __expf(m1 - mn1);
        m0 = mn0; m1 = mn1;
        l0 *= cr0; l1 *= cr1;
        #pragma unroll
        for (int nt = 0; nt < 8; nt++) {
            o[nt][0] *= cr0; o[nt][1] *= cr0;
            o[nt][2] *= cr1; o[nt][3] *= cr1;
        }

        // ---- exp, row-sum, convert P to A-fragment layout via shuffles ----
        const int srcA = (lane & 28) | (t >> 1);
        const int srcB = srcA | 2;
        const bool odd = (t & 1);
        unsigned pa[8][4];
        float ls0 = 0.f, ls1 = 0.f;
        #pragma unroll
        for (int nt = 0; nt < 8; nt++) {
            float p0 = __expf(s[nt][0] - mn0);
            float p1 = __expf(s[nt][1] - mn0);
            float p2 = __expf(s[nt][2] - mn1);
            float p3 = __expf(s[nt][3] - mn1);
            ls0 += p0 + p1; ls1 += p2 + p3;
            unsigned e0 = f2tf32(p0), e1 = f2tf32(p1);
            unsigned e2 = f2tf32(p2), e3 = f2tf32(p3);
            unsigned u0 = __shfl_sync(FULLMASK, e0, srcA);
            unsigned u1 = __shfl_sync(FULLMASK, e1, srcA);
            unsigned u2 = __shfl_sync(FULLMASK, e2, srcA);
            unsigned u3 = __shfl_sync(FULLMASK, e3, srcA);
            unsigned w0 = __shfl_sync(FULLMASK, e0, srcB);
            unsigned w1 = __shfl_sync(FULLMASK, e1, srcB);
            unsigned w2 = __shfl_sync(FULLMASK, e2, srcB);
            unsigned w3 = __shfl_sync(FULLMASK, e3, srcB);
            pa[nt][0] = odd ? u1 : u0;
            pa[nt][1] = odd ? u3 : u2;
            pa[nt][2] = odd ? w1 : w0;
            pa[nt][3] = odd ? w3 : w2;
        }
        ls0 += __shfl_xor_sync(FULLMASK, ls0, 1);
        ls0 += __shfl_xor_sync(FULLMASK, ls0, 2);
        ls1 += __shfl_xor_sync(FULLMASK, ls1, 1);
        ls1 += __shfl_xor_sync(FULLMASK, ls1, 2);
        l0 += ls0; l1 += ls1;

        // ---- O += P @ V ----
        #pragma unroll
        for (int nd = 0; nd < 8; nd++) {
            #pragma unroll
            for (int kj = 0; kj < 8; kj++) {
                unsigned b0 = v_u[(8 * kj + t)     * VSTRIDE + 8 * nd + g];
                unsigned b1 = v_u[(8 * kj + t + 4) * VSTRIDE + 8 * nd + g];
                mma_tf32(o[nd], pa[kj], b0, b1);
            }
        }
        __syncthreads();
    }

    // ---- normalize + store in (B,H,S,HD) layout ----
    const float inv0 = 1.f / l0;
    const float inv1 = 1.f / l1;
    const size_t r0 = (size_t)(b * HH + h) * SS + q0 + w * 16 + g;
    float* o0 = out + r0 * HDD;
    float* o1 = o0 + (size_t)8 * HDD;
    #pragma unroll
    for (int nt = 0; nt < 8; nt++) {
        int col = 8 * nt + 2 * t;
        float2 t0 = make_float2(o[nt][0] * inv0, o[nt][1] * inv0);
        float2 t1 = make_float2(o[nt][2] * inv1, o[nt][3] * inv1);
        *(float2*)&o0[col] = t0;
        *(float2*)&o1[col] = t1;
    }
}

// ---------------------------------------------------------------------------
extern "C" void kernel_launch(void* const* d_in, const int* in_sizes, int n_in,
                              void* d_out, int out_size)
{
    const float* x    = (const float*)d_in[0];
    const float* y    = (const float*)d_in[1];
    const float* W_kv = (const float*)d_in[2];
    const float* b_kv = (const float*)d_in[3];
    const float* W_q  = (const float*)d_in[4];
    const float* b_q  = (const float*)d_in[5];
    const float* W_o  = (const float*)d_in[6];
    const float* b_o  = (const float*)d_in[7];
    float* out = (float*)d_out;

    float *kvp, *qp, *avp;
    cudaGetSymbolAddress((void**)&kvp, g_kv);
    cudaGetSymbolAddress((void**)&qp,  g_q);
    cudaGetSymbolAddress((void**)&avp, g_av);

    dim3 blk(256);

    // kv = x @ W_kv + b_kv   [4096 x 2048]
    gemm_bias_kernel<<<dim3((2 * DD) / GBN, MR / GBM), blk>>>(
        x, W_kv, b_kv, kvp, MR, 2 * DD, DD);
    // q = y @ W_q + b_q      [4096 x 1024]
    gemm_bias_kernel<<<dim3(DD / GBN, MR / GBM), blk>>>(
        y, W_q, b_q, qp, MR, DD, DD);

    // fused tensor-core attention -> values in (B,H,S,HD) layout
    attn_tc_kernel<<<dim3(SS / 128, BB * HH), blk>>>(qp, kvp, avp);

    // out = values @ W_o + b_o [4096 x 1024]
    gemm_bias_kernel<<<dim3(DD / GBN, MR / GBM), blk>>>(
        avp, W_o, b_o, out, MR, DD, DD);
}

// round 4
// speedup vs baseline: 10.5863x; 1.8996x over previous
#include <cuda_runtime.h>
#include <math.h>

#define BB 2
#define SS 2048
#define DD 1024
#define HH 16
#define HDD 64
#define MR (BB*SS)   // 4096 rows

// Scratch (allocation-free rule: __device__ globals)
__device__ __align__(16) float g_kv[MR * 2 * DD];  // 4096 x 2048
__device__ __align__(16) float g_q [MR * DD];      // 4096 x 1024
__device__ __align__(16) float g_av[MR * DD];      // 4096 x 1024 (B,H,S,HD layout!)

#define FULLMASK 0xffffffffu

__device__ __forceinline__ unsigned f2tf32(float f) {
    unsigned u;
    asm("cvt.rna.tf32.f32 %0, %1;" : "=r"(u) : "f"(f));
    return u;
}

__device__ __forceinline__ void mma_tf32(float* d, const unsigned* a,
                                         unsigned b0, unsigned b1) {
    asm volatile(
        "mma.sync.aligned.m16n8k8.row.col.f32.tf32.tf32.f32 "
        "{%0,%1,%2,%3}, {%4,%5,%6,%7}, {%8,%9}, {%0,%1,%2,%3};\n"
        : "+f"(d[0]), "+f"(d[1]), "+f"(d[2]), "+f"(d[3])
        : "r"(a[0]), "r"(a[1]), "r"(a[2]), "r"(a[3]), "r"(b0), "r"(b1));
}

// ---------------------------------------------------------------------------
// Tensor-core tf32 GEMM: C[M,N] = A[M,K] @ B[K,N] + bias[N]
// 128x128 block tile, BK=32, 8 warps (4 m x 2 n), warp tile 32x64.
// As[m][k] stride 36: fragment read bank = 4g+t  (conflict-free)
// Bs[k][n] stride 136: fragment read bank = 8t+g (conflict-free)
// ---------------------------------------------------------------------------
#define TBM 128
#define TBN 128
#define TBK 32
#define ASTR 36
#define BSTR 136

__global__ __launch_bounds__(256, 2) void gemm_tc_kernel(
    const float* __restrict__ A, const float* __restrict__ Bm,
    const float* __restrict__ bias, float* __restrict__ C,
    int M, int N, int K)
{
    __shared__ unsigned As[TBM * ASTR];
    __shared__ unsigned Bs[TBK * BSTR];

    const int tid  = threadIdx.x;
    const int w    = tid >> 5;
    const int lane = tid & 31;
    const int g    = lane >> 2;
    const int t    = lane & 3;
    const int wm   = (w & 3) * 32;   // warp m-offset within block tile
    const int wn   = (w >> 2) * 64;  // warp n-offset within block tile
    const int brow = blockIdx.y * TBM;
    const int bcol = blockIdx.x * TBN;

    float acc[2][8][4];
    #pragma unroll
    for (int mt = 0; mt < 2; mt++)
        #pragma unroll
        for (int nt = 0; nt < 8; nt++)
            #pragma unroll
            for (int j = 0; j < 4; j++) acc[mt][nt][j] = 0.f;

    for (int k0 = 0; k0 < K; k0 += TBK) {
        // A tile: 128 x 32, row-major into As[m][k], cvt tf32 at store
        #pragma unroll
        for (int it = 0; it < 4; it++) {
            int i  = it * 256 + tid;
            int m  = i >> 3;
            int c4 = (i & 7) * 4;
            float4 a = *(const float4*)(A + (size_t)(brow + m) * K + k0 + c4);
            unsigned* dst = &As[m * ASTR + c4];
            dst[0] = f2tf32(a.x); dst[1] = f2tf32(a.y);
            dst[2] = f2tf32(a.z); dst[3] = f2tf32(a.w);
        }
        // B tile: 32 x 128, row-major into Bs[k][n], cvt tf32 at store
        #pragma unroll
        for (int it = 0; it < 4; it++) {
            int i  = it * 256 + tid;
            int kk = i >> 5;
            int c4 = (i & 31) * 4;
            float4 bv = *(const float4*)(Bm + (size_t)(k0 + kk) * N + bcol + c4);
            unsigned* dst = &Bs[kk * BSTR + c4];
            dst[0] = f2tf32(bv.x); dst[1] = f2tf32(bv.y);
            dst[2] = f2tf32(bv.z); dst[3] = f2tf32(bv.w);
        }
        __syncthreads();

        #pragma unroll
        for (int ks = 0; ks < TBK / 8; ks++) {
            unsigned af[2][4];
            #pragma unroll
            for (int mt = 0; mt < 2; mt++) {
                const unsigned* ab = &As[(wm + mt * 16) * ASTR + ks * 8];
                af[mt][0] = ab[g * ASTR + t];
                af[mt][1] = ab[(g + 8) * ASTR + t];
                af[mt][2] = ab[g * ASTR + t + 4];
                af[mt][3] = ab[(g + 8) * ASTR + t + 4];
            }
            const unsigned* bb0 = &Bs[(ks * 8 + t) * BSTR + wn + g];
            const unsigned* bb1 = &Bs[(ks * 8 + t + 4) * BSTR + wn + g];
            #pragma unroll
            for (int nt = 0; nt < 8; nt++) {
                unsigned b0 = bb0[nt * 8];
                unsigned b1 = bb1[nt * 8];
                mma_tf32(acc[0][nt], af[0], b0, b1);
                mma_tf32(acc[1][nt], af[1], b0, b1);
            }
        }
        __syncthreads();
    }

    // Epilogue: bias add, float2 stores
    #pragma unroll
    for (int mt = 0; mt < 2; mt++) {
        const size_t r0 = (size_t)(brow + wm + mt * 16 + g);
        float* c0 = C + r0 * N + bcol + wn;
        float* c1 = c0 + (size_t)8 * N;
        const float* bp = bias + bcol + wn;
        #pragma unroll
        for (int nt = 0; nt < 8; nt++) {
            int col = nt * 8 + 2 * t;
            float bx = bp[col], by = bp[col + 1];
            float2 v0 = make_float2(acc[mt][nt][0] + bx, acc[mt][nt][1] + by);
            float2 v1 = make_float2(acc[mt][nt][2] + bx, acc[mt][nt][3] + by);
            *(float2*)&c0[col] = v0;
            *(float2*)&c1[col] = v1;
        }
    }
}

// ---------------------------------------------------------------------------
// Tensor-core flash attention (tf32 mma.sync m16n8k8, fp32 accum).
// BQ=128 (8 warps x 16 rows), BK=64, HD=64.
// Output written in (B, H, S, HD) contiguous layout (reference reshapes
// the (b,h,q,hd) einsum result directly without re-transposing heads).
// ---------------------------------------------------------------------------
#define KSTRIDE 68
#define VSTRIDE 72

__global__ __launch_bounds__(256, 1) void attn_tc_kernel(
    const float* __restrict__ q, const float* __restrict__ kv,
    float* __restrict__ out)
{
    __shared__ unsigned k_u[64 * KSTRIDE];
    __shared__ unsigned v_u[64 * VSTRIDE];

    const int tid  = threadIdx.x;
    const int w    = tid >> 5;
    const int lane = tid & 31;
    const int g    = lane >> 2;
    const int t    = lane & 3;
    const int bh   = blockIdx.y;
    const int b    = bh / HH;
    const int h    = bh % HH;
    const int q0   = blockIdx.x * 128;

    // Q fragments (held in registers for the whole KV loop)
    unsigned qa[8][4];
    {
        const float* q0p = q + (size_t)(b * SS + q0 + w * 16 + g) * DD + h * HDD;
        const float* q1p = q0p + (size_t)8 * DD;
        #pragma unroll
        for (int kj = 0; kj < 8; kj++) {
            qa[kj][0] = f2tf32(q0p[8 * kj + t]     * 0.125f);
            qa[kj][1] = f2tf32(q1p[8 * kj + t]     * 0.125f);
            qa[kj][2] = f2tf32(q0p[8 * kj + t + 4] * 0.125f);
            qa[kj][3] = f2tf32(q1p[8 * kj + t + 4] * 0.125f);
        }
    }

    float o[8][4];
    #pragma unroll
    for (int i = 0; i < 8; i++)
        #pragma unroll
        for (int j = 0; j < 4; j++) o[i][j] = 0.f;
    float m0 = -INFINITY, m1 = -INFINITY, l0 = 0.f, l1 = 0.f;

    const float* kvbase = kv + (size_t)b * SS * (2 * DD) + h * (2 * HDD);

    for (int kt = 0; kt < SS; kt += 64) {
        #pragma unroll
        for (int it = 0; it < 4; it++) {
            int idx = it * 256 + tid;
            int row = idx >> 4;
            int c4  = (idx & 15) * 4;
            const float* src = kvbase + (size_t)(kt + row) * (2 * DD) + c4;
            float4 kf = *(const float4*)src;
            float4 vf = *(const float4*)(src + HDD);
            uint4 ku = make_uint4(f2tf32(kf.x), f2tf32(kf.y),
                                  f2tf32(kf.z), f2tf32(kf.w));
            uint4 vu = make_uint4(f2tf32(vf.x), f2tf32(vf.y),
                                  f2tf32(vf.z), f2tf32(vf.w));
            *(uint4*)&k_u[row * KSTRIDE + c4] = ku;
            *(uint4*)&v_u[row * VSTRIDE + c4] = vu;
        }
        __syncthreads();

        // S = (Q * scale) @ K^T
        float s[8][4];
        #pragma unroll
        for (int nt = 0; nt < 8; nt++) {
            s[nt][0] = s[nt][1] = s[nt][2] = s[nt][3] = 0.f;
            const unsigned* krow = &k_u[(8 * nt + g) * KSTRIDE];
            #pragma unroll
            for (int kj = 0; kj < 8; kj++) {
                unsigned b0 = krow[8 * kj + t];
                unsigned b1 = krow[8 * kj + t + 4];
                mma_tf32(s[nt], qa[kj], b0, b1);
            }
        }

        // Online softmax (rows r0 = 16w+g, r1 = r0+8)
        float rmax0 = -INFINITY, rmax1 = -INFINITY;
        #pragma unroll
        for (int nt = 0; nt < 8; nt++) {
            rmax0 = fmaxf(rmax0, fmaxf(s[nt][0], s[nt][1]));
            rmax1 = fmaxf(rmax1, fmaxf(s[nt][2], s[nt][3]));
        }
        rmax0 = fmaxf(rmax0, __shfl_xor_sync(FULLMASK, rmax0, 1));
        rmax0 = fmaxf(rmax0, __shfl_xor_sync(FULLMASK, rmax0, 2));
        rmax1 = fmaxf(rmax1, __shfl_xor_sync(FULLMASK, rmax1, 1));
        rmax1 = fmaxf(rmax1, __shfl_xor_sync(FULLMASK, rmax1, 2));

        const float mn0 = fmaxf(m0, rmax0);
        const float mn1 = fmaxf(m1, rmax1);
        const float cr0 = __expf(m0 - mn0);
        const float cr1 = __expf(m1 - mn1);
        m0 = mn0; m1 = mn1;
        l0 *= cr0; l1 *= cr1;
        #pragma unroll
        for (int nt = 0; nt < 8; nt++) {
            o[nt][0] *= cr0; o[nt][1] *= cr0;
            o[nt][2] *= cr1; o[nt][3] *= cr1;
        }

        // exp, row-sum, P -> A-fragment layout via shuffles
        const int srcA = (lane & 28) | (t >> 1);
        const int srcB = srcA | 2;
        const bool odd = (t & 1);
        unsigned pa[8][4];
        float ls0 = 0.f, ls1 = 0.f;
        #pragma unroll
        for (int nt = 0; nt < 8; nt++) {
            float p0 = __expf(s[nt][0] - mn0);
            float p1 = __expf(s[nt][1] - mn0);
            float p2 = __expf(s[nt][2] - mn1);
            float p3 = __expf(s[nt][3] - mn1);
            ls0 += p0 + p1; ls1 += p2 + p3;
            unsigned e0 = f2tf32(p0), e1 = f2tf32(p1);
            unsigned e2 = f2tf32(p2), e3 = f2tf32(p3);
            unsigned u0 = __shfl_sync(FULLMASK, e0, srcA);
            unsigned u1 = __shfl_sync(FULLMASK, e1, srcA);
            unsigned u2 = __shfl_sync(FULLMASK, e2, srcA);
            unsigned u3 = __shfl_sync(FULLMASK, e3, srcA);
            unsigned w0 = __shfl_sync(FULLMASK, e0, srcB);
            unsigned w1 = __shfl_sync(FULLMASK, e1, srcB);
            unsigned w2 = __shfl_sync(FULLMASK, e2, srcB);
            unsigned w3 = __shfl_sync(FULLMASK, e3, srcB);
            pa[nt][0] = odd ? u1 : u0;
            pa[nt][1] = odd ? u3 : u2;
            pa[nt][2] = odd ? w1 : w0;
            pa[nt][3] = odd ? w3 : w2;
        }
        ls0 += __shfl_xor_sync(FULLMASK, ls0, 1);
        ls0 += __shfl_xor_sync(FULLMASK, ls0, 2);
        ls1 += __shfl_xor_sync(FULLMASK, ls1, 1);
        ls1 += __shfl_xor_sync(FULLMASK, ls1, 2);
        l0 += ls0; l1 += ls1;

        // O += P @ V
        #pragma unroll
        for (int nd = 0; nd < 8; nd++) {
            #pragma unroll
            for (int kj = 0; kj < 8; kj++) {
                unsigned b0 = v_u[(8 * kj + t)     * VSTRIDE + 8 * nd + g];
                unsigned b1 = v_u[(8 * kj + t + 4) * VSTRIDE + 8 * nd + g];
                mma_tf32(o[nd], pa[kj], b0, b1);
            }
        }
        __syncthreads();
    }

    // normalize + store in (B,H,S,HD) layout
    const float inv0 = 1.f / l0;
    const float inv1 = 1.f / l1;
    const size_t r0 = (size_t)(b * HH + h) * SS + q0 + w * 16 + g;
    float* o0 = out + r0 * HDD;
    float* o1 = o0 + (size_t)8 * HDD;
    #pragma unroll
    for (int nt = 0; nt < 8; nt++) {
        int col = 8 * nt + 2 * t;
        float2 t0 = make_float2(o[nt][0] * inv0, o[nt][1] * inv0);
        float2 t1 = make_float2(o[nt][2] * inv1, o[nt][3] * inv1);
        *(float2*)&o0[col] = t0;
        *(float2*)&o1[col] = t1;
    }
}

// ---------------------------------------------------------------------------
extern "C" void kernel_launch(void* const* d_in, const int* in_sizes, int n_in,
                              void* d_out, int out_size)
{
    const float* x    = (const float*)d_in[0];
    const float* y    = (const float*)d_in[1];
    const float* W_kv = (const float*)d_in[2];
    const float* b_kv = (const float*)d_in[3];
    const float* W_q  = (const float*)d_in[4];
    const float* b_q  = (const float*)d_in[5];
    const float* W_o  = (const float*)d_in[6];
    const float* b_o  = (const float*)d_in[7];
    float* out = (float*)d_out;

    float *kvp, *qp, *avp;
    cudaGetSymbolAddress((void**)&kvp, g_kv);
    cudaGetSymbolAddress((void**)&qp,  g_q);
    cudaGetSymbolAddress((void**)&avp, g_av);

    dim3 blk(256);

    // kv = x @ W_kv + b_kv   [4096 x 2048]
    gemm_tc_kernel<<<dim3((2 * DD) / TBN, MR / TBM), blk>>>(
        x, W_kv, b_kv, kvp, MR, 2 * DD, DD);
    // q = y @ W_q + b_q      [4096 x 1024]
    gemm_tc_kernel<<<dim3(DD / TBN, MR / TBM), blk>>>(
        y, W_q, b_q, qp, MR, DD, DD);

    // fused tensor-core attention -> values in (B,H,S,HD) layout
    attn_tc_kernel<<<dim3(SS / 128, BB * HH), blk>>>(qp, kvp, avp);

    // out = values @ W_o + b_o [4096 x 1024]
    gemm_tc_kernel<<<dim3(DD / TBN, MR / TBM), blk>>>(
        avp, W_o, b_o, out, MR, DD, DD);
}

// round 5
// speedup vs baseline: 10.8574x; 1.0256x over previous
#include <cuda_runtime.h>
#include <math.h>

#define BB 2
#define SS 2048
#define DD 1024
#define HH 16
#define HDD 64
#define MR (BB*SS)   // 4096 rows

// Scratch (allocation-free rule: __device__ globals)
__device__ __align__(16) float    g_kv[MR * 2 * DD];   // kv proj out (tf32-rounded fp32)
__device__ __align__(16) float    g_q [MR * DD];       // q  proj out (tf32-rounded fp32)
__device__ __align__(16) float    g_av[MR * DD];       // attn out, (B,H,S,HD) layout, rounded
__device__ __align__(16) unsigned g_xc  [MR * DD];     // x     pre-rounded tf32 bits
__device__ __align__(16) unsigned g_yc  [MR * DD];     // y     pre-rounded
__device__ __align__(16) unsigned g_wkvc[DD * 2 * DD]; // W_kv  pre-rounded
__device__ __align__(16) unsigned g_wqc [DD * DD];     // W_q   pre-rounded
__device__ __align__(16) unsigned g_woc [DD * DD];     // W_o   pre-rounded

#define FULLMASK 0xffffffffu

__device__ __forceinline__ unsigned f2tf32(float f) {
    unsigned u;
    asm("cvt.rna.tf32.f32 %0, %1;" : "=r"(u) : "f"(f));
    return u;
}

__device__ __forceinline__ void mma_tf32(float* d, const unsigned* a,
                                         unsigned b0, unsigned b1) {
    asm volatile(
        "mma.sync.aligned.m16n8k8.row.col.f32.tf32.tf32.f32 "
        "{%0,%1,%2,%3}, {%4,%5,%6,%7}, {%8,%9}, {%0,%1,%2,%3};\n"
        : "+f"(d[0]), "+f"(d[1]), "+f"(d[2]), "+f"(d[3])
        : "r"(a[0]), "r"(a[1]), "r"(a[2]), "r"(a[3]), "r"(b0), "r"(b1));
}

__device__ __forceinline__ void cp16(void* dst_smem, const void* src) {
    unsigned d = (unsigned)__cvta_generic_to_shared(dst_smem);
    asm volatile("cp.async.cg.shared.global [%0], [%1], 16;\n" :: "r"(d), "l"(src));
}
__device__ __forceinline__ void cp_commit() {
    asm volatile("cp.async.commit_group;\n");
}
template <int N> __device__ __forceinline__ void cp_wait() {
    asm volatile("cp.async.wait_group %0;\n" :: "n"(N));
}

// ---------------------------------------------------------------------------
// Pre-round pass: fp32 -> tf32-rna bit patterns (vectorized)
// ---------------------------------------------------------------------------
__global__ __launch_bounds__(256) void cvt_tf32_kernel(
    const float* __restrict__ src, unsigned* __restrict__ dst, int n4)
{
    int i = blockIdx.x * 256 + threadIdx.x;
    if (i < n4) {
        float4 v = *(const float4*)(src + 4 * (size_t)i);
        uint4 u = make_uint4(f2tf32(v.x), f2tf32(v.y), f2tf32(v.z), f2tf32(v.w));
        *(uint4*)(dst + 4 * (size_t)i) = u;
    }
}

// ---------------------------------------------------------------------------
// Tensor-core tf32 GEMM, 2-stage cp.async double-buffered.
// Inputs are pre-rounded tf32 bit patterns (no cvt in the loop).
// 128x128 block tile, BK=32, 8 warps (4m x 2n), warp tile 32x64.
// As[m][k] stride 36 (frag bank 4g+t, conflict-free)
// Bs[k][n] stride 136 (frag bank 8t+g, conflict-free)
// ROUND: epilogue pre-rounds output to tf32 precision for the next consumer.
// ---------------------------------------------------------------------------
#define TBM 128
#define TBN 128
#define TBK 32
#define ASTR 36
#define BSTR 136
#define ABUF (TBM * ASTR)   // 4608 words
#define BBUF (TBK * BSTR)   // 4352 words
#define GEMM_SMEM ((2 * ABUF + 2 * BBUF) * 4)  // 71680 bytes

template <bool ROUND>
__global__ __launch_bounds__(256) void gemm_tc_kernel(
    const unsigned* __restrict__ A, const unsigned* __restrict__ Bm,
    const float* __restrict__ bias, float* __restrict__ C,
    int M, int N, int K)
{
    extern __shared__ unsigned smg[];
    unsigned* As = smg;                 // [2][ABUF]
    unsigned* Bs = smg + 2 * ABUF;      // [2][BBUF]

    const int tid  = threadIdx.x;
    const int w    = tid >> 5;
    const int lane = tid & 31;
    const int g    = lane >> 2;
    const int t    = lane & 3;
    const int wm   = (w & 3) * 32;
    const int wn   = (w >> 2) * 64;
    const int brow = blockIdx.y * TBM;
    const int bcol = blockIdx.x * TBN;

    float acc[2][8][4];
    #pragma unroll
    for (int mt = 0; mt < 2; mt++)
        #pragma unroll
        for (int nt = 0; nt < 8; nt++)
            #pragma unroll
            for (int j = 0; j < 4; j++) acc[mt][nt][j] = 0.f;

    // async tile loader
    auto load_tile = [&](int k0, int buf) {
        #pragma unroll
        for (int it = 0; it < 4; it++) {
            int i  = it * 256 + tid;
            int m  = i >> 3;
            int c4 = (i & 7) * 4;
            cp16(&As[buf * ABUF + m * ASTR + c4],
                 A + (size_t)(brow + m) * K + k0 + c4);
        }
        #pragma unroll
        for (int it = 0; it < 4; it++) {
            int i  = it * 256 + tid;
            int kk = i >> 5;
            int c4 = (i & 31) * 4;
            cp16(&Bs[buf * BBUF + kk * BSTR + c4],
                 Bm + (size_t)(k0 + kk) * N + bcol + c4);
        }
        cp_commit();
    };

    load_tile(0, 0);
    int buf = 0;
    for (int k0 = 0; k0 < K; k0 += TBK, buf ^= 1) {
        if (k0 + TBK < K) { load_tile(k0 + TBK, buf ^ 1); cp_wait<1>(); }
        else              { cp_wait<0>(); }
        __syncthreads();

        const unsigned* Ab = &As[buf * ABUF];
        const unsigned* Bb = &Bs[buf * BBUF];
        #pragma unroll
        for (int ks = 0; ks < TBK / 8; ks++) {
            unsigned af[2][4];
            #pragma unroll
            for (int mt = 0; mt < 2; mt++) {
                const unsigned* ab = &Ab[(wm + mt * 16) * ASTR + ks * 8];
                af[mt][0] = ab[g * ASTR + t];
                af[mt][1] = ab[(g + 8) * ASTR + t];
                af[mt][2] = ab[g * ASTR + t + 4];
                af[mt][3] = ab[(g + 8) * ASTR + t + 4];
            }
            const unsigned* bb0 = &Bb[(ks * 8 + t) * BSTR + wn + g];
            const unsigned* bb1 = &Bb[(ks * 8 + t + 4) * BSTR + wn + g];
            #pragma unroll
            for (int nt = 0; nt < 8; nt++) {
                unsigned b0 = bb0[nt * 8];
                unsigned b1 = bb1[nt * 8];
                mma_tf32(acc[0][nt], af[0], b0, b1);
                mma_tf32(acc[1][nt], af[1], b0, b1);
            }
        }
        __syncthreads();
    }

    // Epilogue: bias add (+ optional tf32 pre-round), float2 stores
    #pragma unroll
    for (int mt = 0; mt < 2; mt++) {
        const size_t r0 = (size_t)(brow + wm + mt * 16 + g);
        float* c0 = C + r0 * N + bcol + wn;
        float* c1 = c0 + (size_t)8 * N;
        const float* bp = bias + bcol + wn;
        #pragma unroll
        for (int nt = 0; nt < 8; nt++) {
            int col = nt * 8 + 2 * t;
            float bx = bp[col], by = bp[col + 1];
            float v00 = acc[mt][nt][0] + bx, v01 = acc[mt][nt][1] + by;
            float v10 = acc[mt][nt][2] + bx, v11 = acc[mt][nt][3] + by;
            if (ROUND) {
                v00 = __uint_as_float(f2tf32(v00));
                v01 = __uint_as_float(f2tf32(v01));
                v10 = __uint_as_float(f2tf32(v10));
                v11 = __uint_as_float(f2tf32(v11));
            }
            *(float2*)&c0[col] = make_float2(v00, v01);
            *(float2*)&c1[col] = make_float2(v10, v11);
        }
    }
}

// ---------------------------------------------------------------------------
// Tensor-core flash attention, 2-stage cp.async double-buffered KV tiles.
// q and kv are pre-rounded to tf32 precision by the producer GEMMs, so raw
// bits feed the MMAs directly. Output written (B,H,S,HD)-contiguous and
// pre-rounded for the o-projection.
// ---------------------------------------------------------------------------
#define KSTRIDE 68
#define VSTRIDE 72
#define KBUF (64 * KSTRIDE)   // 4352 words
#define VBUF (64 * VSTRIDE)   // 4608 words
#define ATTN_SMEM ((2 * KBUF + 2 * VBUF) * 4)  // 71680 bytes

__global__ __launch_bounds__(256) void attn_tc_kernel(
    const float* __restrict__ q, const float* __restrict__ kv,
    float* __restrict__ out)
{
    extern __shared__ unsigned sma[];
    unsigned* k_u = sma;              // [2][KBUF]
    unsigned* v_u = sma + 2 * KBUF;   // [2][VBUF]

    const int tid  = threadIdx.x;
    const int w    = tid >> 5;
    const int lane = tid & 31;
    const int g    = lane >> 2;
    const int t    = lane & 3;
    const int bh   = blockIdx.y;
    const int b    = bh / HH;
    const int h    = bh % HH;
    const int q0   = blockIdx.x * 128;

    const float* kvbase = kv + (size_t)b * SS * (2 * DD) + h * (2 * HDD);

    auto load_kv = [&](int kt, int buf) {
        #pragma unroll
        for (int it = 0; it < 4; it++) {
            int idx = it * 256 + tid;
            int row = idx >> 4;
            int c4  = (idx & 15) * 4;
            const float* src = kvbase + (size_t)(kt + row) * (2 * DD) + c4;
            cp16(&k_u[buf * KBUF + row * KSTRIDE + c4], src);
            cp16(&v_u[buf * VBUF + row * VSTRIDE + c4], src + HDD);
        }
        cp_commit();
    };

    load_kv(0, 0);

    // Q fragments (pre-rounded; x0.125 is exponent-only => stays tf32-exact)
    unsigned qa[8][4];
    {
        const float* q0p = q + (size_t)(b * SS + q0 + w * 16 + g) * DD + h * HDD;
        const float* q1p = q0p + (size_t)8 * DD;
        #pragma unroll
        for (int kj = 0; kj < 8; kj++) {
            qa[kj][0] = __float_as_uint(q0p[8 * kj + t]     * 0.125f);
            qa[kj][1] = __float_as_uint(q1p[8 * kj + t]     * 0.125f);
            qa[kj][2] = __float_as_uint(q0p[8 * kj + t + 4] * 0.125f);
            qa[kj][3] = __float_as_uint(q1p[8 * kj + t + 4] * 0.125f);
        }
    }

    float o[8][4];
    #pragma unroll
    for (int i = 0; i < 8; i++)
        #pragma unroll
        for (int j = 0; j < 4; j++) o[i][j] = 0.f;
    float m0 = -INFINITY, m1 = -INFINITY, l0 = 0.f, l1 = 0.f;

    int buf = 0;
    for (int kt = 0; kt < SS; kt += 64, buf ^= 1) {
        if (kt + 64 < SS) { load_kv(kt + 64, buf ^ 1); cp_wait<1>(); }
        else              { cp_wait<0>(); }
        __syncthreads();

        const unsigned* kb = &k_u[buf * KBUF];
        const unsigned* vb = &v_u[buf * VBUF];

        // S = (Q * scale) @ K^T
        float s[8][4];
        #pragma unroll
        for (int nt = 0; nt < 8; nt++) {
            s[nt][0] = s[nt][1] = s[nt][2] = s[nt][3] = 0.f;
            const unsigned* krow = &kb[(8 * nt + g) * KSTRIDE];
            #pragma unroll
            for (int kj = 0; kj < 8; kj++) {
                unsigned b0 = krow[8 * kj + t];
                unsigned b1 = krow[8 * kj + t + 4];
                mma_tf32(s[nt], qa[kj], b0, b1);
            }
        }

        // Online softmax (rows r0 = 16w+g, r1 = r0+8)
        float rmax0 = -INFINITY, rmax1 = -INFINITY;
        #pragma unroll
        for (int nt = 0; nt < 8; nt++) {
            rmax0 = fmaxf(rmax0, fmaxf(s[nt][0], s[nt][1]));
            rmax1 = fmaxf(rmax1, fmaxf(s[nt][2], s[nt][3]));
        }
        rmax0 = fmaxf(rmax0, __shfl_xor_sync(FULLMASK, rmax0, 1));
        rmax0 = fmaxf(rmax0, __shfl_xor_sync(FULLMASK, rmax0, 2));
        rmax1 = fmaxf(rmax1, __shfl_xor_sync(FULLMASK, rmax1, 1));
        rmax1 = fmaxf(rmax1, __shfl_xor_sync(FULLMASK, rmax1, 2));

        const float mn0 = fmaxf(m0, rmax0);
        const float mn1 = fmaxf(m1, rmax1);
        const float cr0 = __expf(m0 - mn0);
        const float cr1 = __expf(m1 - mn1);
        m0 = mn0; m1 = mn1;
        l0 *= cr0; l1 *= cr1;
        #pragma unroll
        for (int nt = 0; nt < 8; nt++) {
            o[nt][0] *= cr0; o[nt][1] *= cr0;
            o[nt][2] *= cr1; o[nt][3] *= cr1;
        }

        // exp, row-sum, P -> A-fragment layout via shuffles
        const int srcA = (lane & 28) | (t >> 1);
        const int srcB = srcA | 2;
        const bool odd = (t & 1);
        unsigned pa[8][4];
        float ls0 = 0.f, ls1 = 0.f;
        #pragma unroll
        for (int nt = 0; nt < 8; nt++) {
            float p0 = __expf(s[nt][0] - mn0);
            float p1 = __expf(s[nt][1] - mn0);
            float p2 = __expf(s[nt][2] - mn1);
            float p3 = __expf(s[nt][3] - mn1);
            ls0 += p0 + p1; ls1 += p2 + p3;
            unsigned e0 = f2tf32(p0), e1 = f2tf32(p1);
            unsigned e2 = f2tf32(p2), e3 = f2tf32(p3);
            unsigned u0 = __shfl_sync(FULLMASK, e0, srcA);
            unsigned u1 = __shfl_sync(FULLMASK, e1, srcA);
            unsigned u2 = __shfl_sync(FULLMASK, e2, srcA);
            unsigned u3 = __shfl_sync(FULLMASK, e3, srcA);
            unsigned w0 = __shfl_sync(FULLMASK, e0, srcB);
            unsigned w1 = __shfl_sync(FULLMASK, e1, srcB);
            unsigned w2 = __shfl_sync(FULLMASK, e2, srcB);
            unsigned w3 = __shfl_sync(FULLMASK, e3, srcB);
            pa[nt][0] = odd ? u1 : u0;
            pa[nt][1] = odd ? u3 : u2;
            pa[nt][2] = odd ? w1 : w0;
            pa[nt][3] = odd ? w3 : w2;
        }
        ls0 += __shfl_xor_sync(FULLMASK, ls0, 1);
        ls0 += __shfl_xor_sync(FULLMASK, ls0, 2);
        ls1 += __shfl_xor_sync(FULLMASK, ls1, 1);
        ls1 += __shfl_xor_sync(FULLMASK, ls1, 2);
        l0 += ls0; l1 += ls1;

        // O += P @ V
        #pragma unroll
        for (int nd = 0; nd < 8; nd++) {
            #pragma unroll
            for (int kj = 0; kj < 8; kj++) {
                unsigned b0 = vb[(8 * kj + t)     * VSTRIDE + 8 * nd + g];
                unsigned b1 = vb[(8 * kj + t + 4) * VSTRIDE + 8 * nd + g];
                mma_tf32(o[nd], pa[kj], b0, b1);
            }
        }
        __syncthreads();
    }

    // normalize + pre-round + store in (B,H,S,HD) layout
    const float inv0 = 1.f / l0;
    const float inv1 = 1.f / l1;
    const size_t r0 = (size_t)(b * HH + h) * SS + q0 + w * 16 + g;
    float* o0 = out + r0 * HDD;
    float* o1 = o0 + (size_t)8 * HDD;
    #pragma unroll
    for (int nt = 0; nt < 8; nt++) {
        int col = 8 * nt + 2 * t;
        float2 t0 = make_float2(__uint_as_float(f2tf32(o[nt][0] * inv0)),
                                __uint_as_float(f2tf32(o[nt][1] * inv0)));
        float2 t1 = make_float2(__uint_as_float(f2tf32(o[nt][2] * inv1)),
                                __uint_as_float(f2tf32(o[nt][3] * inv1)));
        *(float2*)&o0[col] = t0;
        *(float2*)&o1[col] = t1;
    }
}

// ---------------------------------------------------------------------------
extern "C" void kernel_launch(void* const* d_in, const int* in_sizes, int n_in,
                              void* d_out, int out_size)
{
    const float* x    = (const float*)d_in[0];
    const float* y    = (const float*)d_in[1];
    const float* W_kv = (const float*)d_in[2];
    const float* b_kv = (const float*)d_in[3];
    const float* W_q  = (const float*)d_in[4];
    const float* b_q  = (const float*)d_in[5];
    const float* W_o  = (const float*)d_in[6];
    const float* b_o  = (const float*)d_in[7];
    float* out = (float*)d_out;

    float *kvp, *qp, *avp;
    unsigned *xc, *yc, *wkvc, *wqc, *woc;
    cudaGetSymbolAddress((void**)&kvp,  g_kv);
    cudaGetSymbolAddress((void**)&qp,   g_q);
    cudaGetSymbolAddress((void**)&avp,  g_av);
    cudaGetSymbolAddress((void**)&xc,   g_xc);
    cudaGetSymbolAddress((void**)&yc,   g_yc);
    cudaGetSymbolAddress((void**)&wkvc, g_wkvc);
    cudaGetSymbolAddress((void**)&wqc,  g_wqc);
    cudaGetSymbolAddress((void**)&woc,  g_woc);

    cudaFuncSetAttribute(gemm_tc_kernel<true>,
        cudaFuncAttributeMaxDynamicSharedMemorySize, GEMM_SMEM);
    cudaFuncSetAttribute(gemm_tc_kernel<false>,
        cudaFuncAttributeMaxDynamicSharedMemorySize, GEMM_SMEM);
    cudaFuncSetAttribute(attn_tc_kernel,
        cudaFuncAttributeMaxDynamicSharedMemorySize, ATTN_SMEM);

    dim3 blk(256);

    // Pre-round inputs to tf32 bit patterns
    cvt_tf32_kernel<<<(MR * DD / 4 + 255) / 256, blk>>>(x, xc, MR * DD / 4);
    cvt_tf32_kernel<<<(MR * DD / 4 + 255) / 256, blk>>>(y, yc, MR * DD / 4);
    cvt_tf32_kernel<<<(DD * 2 * DD / 4 + 255) / 256, blk>>>(W_kv, wkvc, DD * 2 * DD / 4);
    cvt_tf32_kernel<<<(DD * DD / 4 + 255) / 256, blk>>>(W_q, wqc, DD * DD / 4);
    cvt_tf32_kernel<<<(DD * DD / 4 + 255) / 256, blk>>>(W_o, woc, DD * DD / 4);

    // kv = x @ W_kv + b_kv   [4096 x 2048], output pre-rounded
    gemm_tc_kernel<true><<<dim3((2 * DD) / TBN, MR / TBM), blk, GEMM_SMEM>>>(
        xc, wkvc, b_kv, kvp, MR, 2 * DD, DD);
    // q = y @ W_q + b_q      [4096 x 1024], output pre-rounded
    gemm_tc_kernel<true><<<dim3(DD / TBN, MR / TBM), blk, GEMM_SMEM>>>(
        yc, wqc, b_q, qp, MR, DD, DD);

    // fused tensor-core attention -> values in (B,H,S,HD) layout (pre-rounded)
    attn_tc_kernel<<<dim3(SS / 128, BB * HH), blk, ATTN_SMEM>>>(qp, kvp, avp);

    // out = values @ W_o + b_o [4096 x 1024], final output NOT rounded
    gemm_tc_kernel<false><<<dim3(DD / TBN, MR / TBM), blk, GEMM_SMEM>>>(
        (const unsigned*)avp, woc, b_o, out, MR, DD, DD);
}